// round 15
// baseline (speedup 1.0000x reference)
#include <cuda_runtime.h>

#define TT       64
#define NBID     4096                    // N*C
#define DOUT     129
#define BPB      32                      // bids per group: 32*516B = 129 full 128B lines
#define THREADS  512
#define HALF_T   32                      // t-planes per block
#define TSTRIDE  (NBID * DOUT)           // floats between consecutive t planes
#define FLAT     (BPB * DOUT)            // 4128 outputs per t-plane per group

#define LOG2E_HALF 0.72134752044448169f  // 0.5*log2(e)

// dynamic smem layout (floats):
//   [0,8256)      Utab[32 bids][2 ch][129]  (xs overlaid here during load/scan)
//   [8256,12352)  S_t[64 t][64 pairs]
//   [12352,12417) P[65]
//   [12417,12546) dly[129]
//   [12546,12610) S63sh[64]
//   [12610,12674) Lsh[64] (int)
#define SMEM_FLOATS 12674
#define SMEM_BYTES  (SMEM_FLOATS * 4)

struct EmitCtx {
    const float* Utab;
    const float* S_t;
    const float* dly;
    const int*   Lsh;
    float W, Pt0;
    int   b0, t0;
    float* out;
};

__device__ __forceinline__ void emit_one(const EmitCtx& C, int e, float2 uv)
{
    const unsigned eu  = (unsigned)e;
    const unsigned bid = eu / 129u;                 // const-div -> mul+shift
    const unsigned dd  = eu - bid * 129u;

    const float dp = C.dly[dd];
    float del0 = fmaxf(dp, 0.f), del1 = fmaxf(-dp, 0.f);
    float df0  = floorf(del0),   df1  = floorf(del1);
    float r0 = (uv.x < del0 - df0) ? df0 + 1.f : df0;   // stochastic rounding
    float r1 = (uv.y < del1 - df1) ? df1 + 1.f : df1;
    r0 = fminf(r0, (float)C.Lsh[2 * bid]);              // clamp to window
    r1 = fminf(r1, (float)C.Lsh[2 * bid + 1]);
    const int d0 = min(63, max(0, (int)r0));
    const int d1 = min(63, max(0, (int)r1));
    const float ncm = -(C.S_t[(63 - d0) * 64 + 2 * bid] +
                        C.S_t[(63 - d1) * 64 + 2 * bid + 1]) * C.W;

    const float* A = C.Utab + bid * 258 + (64 - d0) + C.t0;   // linear in t
    const float* B = C.Utab + bid * 258 + 129 + (64 - d1) + C.t0;
    float* op = C.out + C.t0 * TSTRIDE + C.b0 * DOUT + e;

    const float a  = 0.60653065971263342f;
    const float m1 = a, m2 = a * a, m3 = m2 * a, m4 = m2 * m2;
    float acc = ncm * C.Pt0;                                  // ncm * a^{t0}

    #pragma unroll
    for (int t4 = 0; t4 < HALF_T; t4 += 4) {
        float v0 = A[t4 + 0] + B[t4 + 0];
        float v1 = A[t4 + 1] + B[t4 + 1];
        float v2 = A[t4 + 2] + B[t4 + 2];
        float v3 = A[t4 + 3] + B[t4 + 3];
        op[0]           = fmaf(acc, m1, v0);   // f(t) = U0+U1 + a^{t+1}*ncm
        op[TSTRIDE]     = fmaf(acc, m2, v1);
        op[2 * TSTRIDE] = fmaf(acc, m3, v2);
        op[3 * TSTRIDE] = fmaf(acc, m4, v3);
        acc *= m4;
        op += 4 * TSTRIDE;
    }
}

__global__ void __launch_bounds__(THREADS, 2)
jeffress_kernel(const float2* __restrict__ inp,         // (T, N*C) float2 over last dim
                const float*  __restrict__ delay_param, // (129)
                const float*  __restrict__ weight,      // scalar
                const float2* __restrict__ u,           // (N*C, 129) float2 over last dim
                float*        __restrict__ out)         // (T, N*C, 129)
{
    extern __shared__ float sm[];
    float* Utab  = sm;                 // 8256; xs (4096 floats) overlaid at front
    float* S_t   = sm + 8256;          // 4096
    float* P     = sm + 12352;         // 65
    float* dly   = sm + 12417;         // 129
    float* S63sh = sm + 12546;         // 64
    int*   Lsh   = (int*)(sm + 12610); // 64

    const int tid = threadIdx.x;
    const int grp = blockIdx.x >> 1;
    const int t0  = (blockIdx.x & 1) * HALF_T;   // this block's t-half
    const int b0  = grp * BPB;

    // ---- stage 32 bids' 64-step series: xs2[t*32+bl] (overlaid in Utab area) ----
    {
        float2* xs2 = (float2*)Utab;
        int e2 = tid;
        #pragma unroll
        for (int r = 0; r < 4; r++, e2 += THREADS) {     // 2048 float2 loads
            int t = e2 >> 5, bl = e2 & 31;
            xs2[t * 32 + bl] = inp[t * NBID + b0 + bl];  // 256B contiguous per warp
        }
    }
    if (tid < 65) P[tid] = exp2f(-LOG2E_HALF * (float)tid);
    if (tid >= 65 && tid < 65 + DOUT) dly[tid - 65] = delay_param[tid - 65];
    __syncthreads();

    // ---- 64 parallel LIF scans + FIRST argmax: lane = pair = 2*bid + ch ----
    if (tid < 64) {
        const float a = 0.60653065971263342f;   // exp(-0.5)
        const float* xsf = Utab;                // xs[t*64 + pair]
        float v = 0.f, best = -1.f;
        int bt = 0;
        #pragma unroll
        for (int t = 0; t < TT; t++) {
            float x = xsf[t * 64 + tid];
            v = v * a + x;
            S_t[t * 64 + tid] = v;
            if (x > best) { best = x; bt = t; }  // strict '>' => first max (jnp.argmax)
        }
        Lsh[tid]   = 63 - bt;
        S63sh[tid] = v;
    }
    __syncthreads();

    const float W = *weight;

    // ---- build Utab[pair][i], i in [0,128):
    //      i in [1,64):   U = S[i]*W                     (t <  d regime)
    //      i in [64,128): U = (S[i-64] + P[i-63]*S63)*W  (t >= d regime)
    {
        const int pair = tid & 63, i0 = tid >> 6;        // i0 in [0,8)
        const float S63 = S63sh[pair];
        #pragma unroll
        for (int k = 0; k < 16; k++) {
            int i = i0 + k * 8;
            float v;
            if (i < 64) v = (i >= 1) ? S_t[i * 64 + pair] * W : 0.f;
            else        v = fmaf(P[i - 63], S63, S_t[(i - 64) * 64 + pair]) * W;
            Utab[pair * 129 + i] = v;                    // 129 stride: conflict-free
        }
    }

    // ---- prefetch all per-thread u values (hide LDG latency fully) ----
    float2 uu[8];
    {
        const float2* ub = u + b0 * DOUT + tid;
        #pragma unroll
        for (int j = 0; j < 8; j++) uu[j] = ub[j * THREADS];
    }
    float2 uu8 = make_float2(0.f, 0.f);
    if (tid < FLAT - 8 * THREADS) uu8 = u[b0 * DOUT + 8 * THREADS + tid];

    __syncthreads();

    EmitCtx C;
    C.Utab = Utab;  C.S_t = S_t;  C.dly = dly;  C.Lsh = Lsh;
    C.W = W;  C.Pt0 = P[t0];  C.b0 = b0;  C.t0 = t0;  C.out = out;

    // ---- emit this block's 32 t-planes; every warp store = full aligned 128B line ----
    #pragma unroll
    for (int j = 0; j < 8; j++)
        emit_one(C, tid + j * THREADS, uu[j]);
    if (tid < FLAT - 8 * THREADS)                       // 32 leftover flat positions
        emit_one(C, tid + 8 * THREADS, uu8);
}

extern "C" void kernel_launch(void* const* d_in, const int* in_sizes, int n_in,
                              void* d_out, int out_size)
{
    const void* p_input = d_in[0];
    const void* p_delay = d_in[1];
    const void* p_w     = d_in[2];
    const void* p_u     = d_in[3];
    for (int i = 0; i < n_in; i++) {
        if (in_sizes[i] == TT * NBID * 2)        p_input = d_in[i];
        else if (in_sizes[i] == DOUT)            p_delay = d_in[i];
        else if (in_sizes[i] == 1)               p_w     = d_in[i];
        else if (in_sizes[i] == NBID * DOUT * 2) p_u     = d_in[i];
    }

    static int attr_done = 0;
    if (!attr_done) {
        cudaFuncSetAttribute(jeffress_kernel,
                             cudaFuncAttributeMaxDynamicSharedMemorySize, SMEM_BYTES);
        attr_done = 1;
    }

    jeffress_kernel<<<(NBID / BPB) * 2, THREADS, SMEM_BYTES>>>(
        (const float2*)p_input,
        (const float*)p_delay,
        (const float*)p_w,
        (const float2*)p_u,
        (float*)d_out);
}

// round 17
// speedup vs baseline: 1.0176x; 1.0176x over previous
#include <cuda_runtime.h>

#define TT       64
#define NBID     4096                    // N*C
#define DOUT     129
#define BPB      32                      // bids per group: 32*516B = 129 full 128B lines
#define THREADS  512
#define HALF_T   32                      // t-planes per block
#define TSTRIDE  (NBID * DOUT)           // floats between consecutive t planes
#define FLAT     (BPB * DOUT)            // 4128 outputs per t-plane per group

#define LOG2E_HALF 0.72134752044448169f  // 0.5*log2(e)

// dynamic smem layout (floats):
//   [0,8256)      Utab[32 bids][2 ch][129]  (xs overlaid here during load/scan)
//   [8256,12352)  S_t[64 t][64 pairs]
//   [12352,12417) P[65]
//   [12417,12546) dly[129]
//   [12546,12610) S63sh[64]
//   [12610,12674) Lsh[64] (int)
#define SMEM_FLOATS 12674
#define SMEM_BYTES  (SMEM_FLOATS * 4)

__global__ void __launch_bounds__(THREADS, 2)
jeffress_kernel(const float2* __restrict__ inp,         // (T, N*C) float2 over last dim
                const float*  __restrict__ delay_param, // (129)
                const float*  __restrict__ weight,      // scalar
                const float2* __restrict__ u,           // (N*C, 129) float2 over last dim
                float*        __restrict__ out)         // (T, N*C, 129)
{
    extern __shared__ float sm[];
    float* Utab  = sm;                 // 8256; xs (4096 floats) overlaid at front
    float* S_t   = sm + 8256;          // 4096
    float* P     = sm + 12352;         // 65
    float* dly   = sm + 12417;         // 129
    float* S63sh = sm + 12546;         // 64
    int*   Lsh   = (int*)(sm + 12610); // 64

    const int tid = threadIdx.x;
    const int grp = blockIdx.x >> 1;
    const int t0  = (blockIdx.x & 1) * HALF_T;   // this block's t-half
    const int b0  = grp * BPB;

    // ---- stage 32 bids' 64-step series: xs2[t*32+bl] (overlaid in Utab area) ----
    {
        float2* xs2 = (float2*)Utab;
        int e2 = tid;
        #pragma unroll
        for (int r = 0; r < 4; r++, e2 += THREADS) {     // 2048 float2 loads
            int t = e2 >> 5, bl = e2 & 31;
            xs2[t * 32 + bl] = inp[t * NBID + b0 + bl];  // 256B contiguous per warp
        }
    }
    if (tid < 65) P[tid] = exp2f(-LOG2E_HALF * (float)tid);
    if (tid >= 65 && tid < 65 + DOUT) dly[tid - 65] = delay_param[tid - 65];
    __syncthreads();

    // ---- 64 parallel LIF scans + FIRST argmax: lane = pair = 2*bid + ch ----
    if (tid < 64) {
        const float a = 0.60653065971263342f;   // exp(-0.5)
        const float* xsf = Utab;                // xs[t*64 + pair]
        float v = 0.f, best = -1.f;
        int bt = 0;
        #pragma unroll
        for (int t = 0; t < TT; t++) {
            float x = xsf[t * 64 + tid];
            v = v * a + x;
            S_t[t * 64 + tid] = v;
            if (x > best) { best = x; bt = t; }  // strict '>' => first max (jnp.argmax)
        }
        Lsh[tid]   = 63 - bt;
        S63sh[tid] = v;
    }
    __syncthreads();

    const float W = *weight;

    // ---- build Utab[pair][i], i in [0,128):
    //      i in [1,64):   U = S[i]*W                     (t <  d regime)
    //      i in [64,128): U = (S[i-64] + P[i-63]*S63)*W  (t >= d regime)
    {
        const int pair = tid & 63, i0 = tid >> 6;        // i0 in [0,8)
        const float S63 = S63sh[pair];
        #pragma unroll
        for (int k = 0; k < 16; k++) {
            int i = i0 + k * 8;
            float v;
            if (i < 64) v = (i >= 1) ? S_t[i * 64 + pair] * W : 0.f;
            else        v = fmaf(P[i - 63], S63, S_t[(i - 64) * 64 + pair]) * W;
            Utab[pair * 129 + i] = v;                    // 129 stride: conflict-free
        }
    }

    // ---- prefetch all per-thread u values (hide LDG latency) ----
    float2 uu[8];
    {
        const float2* ub = u + b0 * DOUT + tid;
        #pragma unroll
        for (int j = 0; j < 8; j++) uu[j] = ub[j * THREADS];
    }
    float2 uu8 = make_float2(2.f, 2.f);                  // u>=2 -> no round-up (safe dummy)
    if (tid < FLAT - 8 * THREADS) uu8 = u[b0 * DOUT + 8 * THREADS + tid];

    __syncthreads();

    // ---- precompute per-j state: packed U-table bases (t0 folded in) + ncm ----
    int   iab[9];
    float ncf[9];
    #pragma unroll
    for (int j = 0; j < 9; j++) {
        const int e = tid + j * THREADS;
        if (j == 8 && tid >= FLAT - 8 * THREADS) { iab[j] = 0; ncf[j] = 0.f; continue; }
        const unsigned eu  = (unsigned)e;
        const unsigned bid = eu / 129u;                  // const-div -> mul+shift
        const unsigned dd  = eu - bid * 129u;
        const float2 uv = (j < 8) ? uu[j] : uu8;

        const float dp = dly[dd];
        float del0 = fmaxf(dp, 0.f), del1 = fmaxf(-dp, 0.f);
        float df0  = floorf(del0),   df1  = floorf(del1);
        float r0 = (uv.x < del0 - df0) ? df0 + 1.f : df0;    // stochastic rounding
        float r1 = (uv.y < del1 - df1) ? df1 + 1.f : df1;
        r0 = fminf(r0, (float)Lsh[2 * bid]);                 // clamp to window
        r1 = fminf(r1, (float)Lsh[2 * bid + 1]);
        const int d0 = min(63, max(0, (int)r0));
        const int d1 = min(63, max(0, (int)r1));
        ncf[j] = -(S_t[(63 - d0) * 64 + 2 * bid] +
                   S_t[(63 - d1) * 64 + 2 * bid + 1]) * W;
        const int ia = bid * 258 + (64 - d0) + t0;           // fits in 16 bits
        const int ib = bid * 258 + 129 + (64 - d1) + t0;
        iab[j] = ia | (ib << 16);
    }

    // ---- emit, t-outer / j-inner: block writes its 16.5KB plane chunk as one
    //      contiguous burst per t -> DRAM row/page-friendly write stream ----
    const float a = 0.60653065971263342f;
    float pt = P[t0 + 1];                                // a^{t+1}, ladder
    float* opb = out + t0 * TSTRIDE + b0 * DOUT + tid;
    const bool extra = (tid < FLAT - 8 * THREADS);

    #pragma unroll 4
    for (int t = 0; t < HALF_T; t++) {
        #pragma unroll
        for (int j = 0; j < 8; j++) {
            const int ab = iab[j];
            const float v = Utab[(ab & 0xFFFF) + t] + Utab[(ab >> 16) + t];
            opb[j * THREADS] = fmaf(ncf[j], pt, v);      // full aligned 128B line/warp
        }
        if (extra) {
            const int ab = iab[8];
            const float v = Utab[(ab & 0xFFFF) + t] + Utab[(ab >> 16) + t];
            opb[8 * THREADS] = fmaf(ncf[8], pt, v);
        }
        pt *= a;
        opb += TSTRIDE;
    }
}

extern "C" void kernel_launch(void* const* d_in, const int* in_sizes, int n_in,
                              void* d_out, int out_size)
{
    const void* p_input = d_in[0];
    const void* p_delay = d_in[1];
    const void* p_w     = d_in[2];
    const void* p_u     = d_in[3];
    for (int i = 0; i < n_in; i++) {
        if (in_sizes[i] == TT * NBID * 2)        p_input = d_in[i];
        else if (in_sizes[i] == DOUT)            p_delay = d_in[i];
        else if (in_sizes[i] == 1)               p_w     = d_in[i];
        else if (in_sizes[i] == NBID * DOUT * 2) p_u     = d_in[i];
    }

    static int attr_done = 0;
    if (!attr_done) {
        cudaFuncSetAttribute(jeffress_kernel,
                             cudaFuncAttributeMaxDynamicSharedMemorySize, SMEM_BYTES);
        attr_done = 1;
    }

    jeffress_kernel<<<(NBID / BPB) * 2, THREADS, SMEM_BYTES>>>(
        (const float2*)p_input,
        (const float*)p_delay,
        (const float*)p_w,
        (const float2*)p_u,
        (float*)d_out);
}